// round 16
// baseline (speedup 1.0000x reference)
#include <cuda_runtime.h>
#include <cuda_bf16.h>

#define NLOC 1024
#define NNEI 64
#define NDIM 128
#define EDIM 64
#define ADIM 64
#define ASEL 20

typedef unsigned long long ull;

// ---------------- scratch (static device memory; no allocation) ----------------
__device__ float g_pself[NLOC * NDIM];
__device__ float g_pW0[NLOC * NDIM];
__device__ float g_pW1[NLOC * NDIM];
__device__ float g_pV0[NLOC * EDIM];
__device__ float g_pV1[NLOC * EDIM];
__device__ float g_pA1[NLOC * EDIM];
__device__ float g_pB1[NLOC * ADIM];
__device__ float g_eproj[NLOC * ASEL * 4 * 64]; // [l][j][A2,A3,B2,B3][64]
__device__ float g_red[NLOC * ASEL * EDIM];
__device__ float g_symin[NLOC * 768];
__device__ float g_nedge[NLOC * NDIM];
// bf16 hi/lo W for the angle MMA A operand: Wcat[n=128][k=64], plain k-major
__device__ unsigned short g_Whi[128 * 64];
__device__ unsigned short g_Wlo[128 * 64];
// bf16 hi/lo W_sym, transposed to [n=128][k=768]
__device__ unsigned short g_WsymH[128 * 768];
__device__ unsigned short g_WsymL[128 * 768];

// ---------------- helpers ----------------
__device__ __forceinline__ float silu_f(float x) { return __fdividef(x, 1.0f + __expf(-x)); }

__device__ __forceinline__ ull pack2(float lo, float hi) {
    ull r;
    asm("mov.b64 %0, {%1, %2};" : "=l"(r) : "f"(lo), "f"(hi));
    return r;
}
__device__ __forceinline__ float sum2(ull v) {
    float lo, hi;
    asm("mov.b64 {%0, %1}, %2;" : "=f"(lo), "=f"(hi) : "l"(v));
    return lo + hi;
}
__device__ __forceinline__ void fma2(ull &acc, ull a, ull b) {
    asm("fma.rn.f32x2 %0, %1, %2, %0;" : "+l"(acc) : "l"(a), "l"(b));
}
__device__ __forceinline__ void lds_2x64(ull &a, ull &b, unsigned saddr) {
    asm volatile("ld.shared.v2.u64 {%0, %1}, [%2];" : "=l"(a), "=l"(b) : "r"(saddr));
}
__device__ __forceinline__ unsigned saddr_of(const void* p) {
    return (unsigned)__cvta_generic_to_shared(p);
}
__device__ __forceinline__ void cp_async16(unsigned sdst, const void* gsrc) {
    asm volatile("cp.async.cg.shared.global [%0], [%1], 16;" :: "r"(sdst), "l"(gsrc));
}
__device__ __forceinline__ void cp_commit() { asm volatile("cp.async.commit_group;"); }
__device__ __forceinline__ void cp_wait0()  { asm volatile("cp.async.wait_group 0;"); }

// bf16 HMMA (base ISA, sm_80+): D[16x8 f32] += A[16x16 bf16] * B[16x8 bf16]
__device__ __forceinline__ void mma16816(float* c, const unsigned* a, const unsigned* b) {
    asm volatile("mma.sync.aligned.m16n8k16.row.col.f32.bf16.bf16.f32 "
        "{%0,%1,%2,%3}, {%4,%5,%6,%7}, {%8,%9}, {%0,%1,%2,%3};"
        : "+f"(c[0]), "+f"(c[1]), "+f"(c[2]), "+f"(c[3])
        : "r"(a[0]), "r"(a[1]), "r"(a[2]), "r"(a[3]), "r"(b[0]), "r"(b[1]));
}
__device__ __forceinline__ void f2_to_bf(float2 v, unsigned &hi, unsigned &lo) {
    __nv_bfloat16 hx = __float2bfloat16_rn(v.x);
    __nv_bfloat16 hy = __float2bfloat16_rn(v.y);
    __nv_bfloat16 lx = __float2bfloat16_rn(v.x - __bfloat162float(hx));
    __nv_bfloat16 ly = __float2bfloat16_rn(v.y - __bfloat162float(hy));
    hi = (unsigned)__bfloat16_as_ushort(hx) | ((unsigned)__bfloat16_as_ushort(hy) << 16);
    lo = (unsigned)__bfloat16_as_ushort(lx) | ((unsigned)__bfloat16_as_ushort(ly) << 16);
}

// ---------------- kernel A: per-node projections (16 nodes / block, pass = blockIdx.y) ----------------
__global__ void __launch_bounds__(128) k_nodeproj(
        const float* __restrict__ node,
        const float* __restrict__ W_self, const float* __restrict__ b_self,
        const float* __restrict__ W_ne,   const float* __restrict__ b_ne,
        const float* __restrict__ W_es,   const float* __restrict__ b_es,
        const float* __restrict__ W_ea1,  const float* __restrict__ b_ea1,
        const float* __restrict__ W_as,   const float* __restrict__ b_as)
{
    const int t    = threadIdx.x;
    const int l0   = blockIdx.x * 16;
    const int pass = blockIdx.y;
    __shared__ __align__(16) float xs[16][NDIM];
    {
        const float4* src = (const float4*)(node + l0 * NDIM);
        float4* dst = (float4*)(&xs[0][0]);
        #pragma unroll
        for (int i = 0; i < 4; i++) dst[t + 128 * i] = src[t + 128 * i];
    }
    __syncthreads();

    float acc[16];
    #pragma unroll
    for (int m = 0; m < 16; m++) acc[m] = 0.f;

    if (pass < 3) {
        const float* W = (pass == 0) ? W_self : ((pass == 1) ? W_ne : (W_ne + NDIM * NDIM));
        for (int k = 0; k < NDIM; k += 4) {
            float w0 = W[(k + 0) * NDIM + t];
            float w1 = W[(k + 1) * NDIM + t];
            float w2 = W[(k + 2) * NDIM + t];
            float w3 = W[(k + 3) * NDIM + t];
            #pragma unroll
            for (int m = 0; m < 16; m++) {
                float4 x = *(const float4*)(&xs[m][k]);
                acc[m] = fmaf(x.x, w0, acc[m]);
                acc[m] = fmaf(x.y, w1, acc[m]);
                acc[m] = fmaf(x.z, w2, acc[m]);
                acc[m] = fmaf(x.w, w3, acc[m]);
            }
        }
        if (pass == 0) {
            float b = b_self[t];
            #pragma unroll
            for (int m = 0; m < 16; m++) g_pself[(l0 + m) * NDIM + t] = silu_f(acc[m] + b);
        } else if (pass == 1) {
            float b = b_ne[t];
            #pragma unroll
            for (int m = 0; m < 16; m++) g_pW0[(l0 + m) * NDIM + t] = acc[m] + b;
        } else {
            #pragma unroll
            for (int m = 0; m < 16; m++) g_pW1[(l0 + m) * NDIM + t] = acc[m];
        }
    } else {
        const int d = t & 63;
        const float* W;
        if (pass == 3) W = W_es + ((t < 64) ? 0 : NDIM * EDIM) + d;
        else           W = ((t < 64) ? W_ea1 : W_as) + 64 * 64 + d;
        for (int k = 0; k < NDIM; k += 4) {
            float w0 = W[(k + 0) * 64];
            float w1 = W[(k + 1) * 64];
            float w2 = W[(k + 2) * 64];
            float w3 = W[(k + 3) * 64];
            #pragma unroll
            for (int m = 0; m < 16; m++) {
                float4 x = *(const float4*)(&xs[m][k]);
                acc[m] = fmaf(x.x, w0, acc[m]);
                acc[m] = fmaf(x.y, w1, acc[m]);
                acc[m] = fmaf(x.z, w2, acc[m]);
                acc[m] = fmaf(x.w, w3, acc[m]);
            }
        }
        if (pass == 3) {
            if (t < 64) {
                float b = b_es[d];
                #pragma unroll
                for (int m = 0; m < 16; m++) g_pV0[(l0 + m) * EDIM + d] = acc[m] + b;
            } else {
                #pragma unroll
                for (int m = 0; m < 16; m++) g_pV1[(l0 + m) * EDIM + d] = acc[m];
            }
        } else {
            if (t < 64) {
                float b = b_ea1[d];
                #pragma unroll
                for (int m = 0; m < 16; m++) g_pA1[(l0 + m) * EDIM + d] = acc[m] + b;
            } else {
                float b = b_as[d];
                #pragma unroll
                for (int m = 0; m < 16; m++) g_pB1[(l0 + m) * ADIM + d] = acc[m] + b;
            }
        }
    }
}

// ---------------- kernel A2: e_ang projections; 1 node / block ----------------
__global__ void __launch_bounds__(256) k_eproj(const float* __restrict__ edge,
                                               const float* __restrict__ W_ea1,
                                               const float* __restrict__ W_as)
{
    const int t  = threadIdx.x;
    const int l  = blockIdx.x;
    const int which = t >> 6;        // 0:A2 1:A3 2:B2 3:B3
    const int d = t & 63;
    const float* Wsrc = ((which < 2) ? W_ea1 : W_as) + ((which & 1) ? 256 * 64 : 192 * 64) + d;
    ull w2[32];
    #pragma unroll
    for (int kk = 0; kk < 32; kk++)
        w2[kk] = pack2(Wsrc[(2 * kk) * 64], Wsrc[(2 * kk + 1) * 64]);

    __shared__ __align__(16) float rows[ASEL][64];
    const unsigned rbase = saddr_of(&rows[0][0]);

    {
        const float4* src = (const float4*)(edge + (size_t)l * NNEI * EDIM);
        float4* dst = (float4*)(&rows[0][0]);
        for (int q = t; q < ASEL * 16; q += 256) dst[q] = src[q];
    }
    __syncthreads();
    for (int j = 0; j < ASEL; j += 2) {
        const unsigned a_j0 = rbase + j * 256;
        const unsigned a_j1 = a_j0 + 256;
        ull a0 = 0, a1 = 0, c0 = 0, c1 = 0;
        #pragma unroll
        for (int kk = 0; kk < 16; kk++) {
            ull x0, x1, y0, y1;
            lds_2x64(x0, x1, a_j0 + kk * 16);
            lds_2x64(y0, y1, a_j1 + kk * 16);
            fma2(a0, w2[2 * kk],     x0);
            fma2(a1, w2[2 * kk + 1], x1);
            fma2(c0, w2[2 * kk],     y0);
            fma2(c1, w2[2 * kk + 1], y1);
        }
        g_eproj[((l * ASEL + j)     * 4 + which) * 64 + d] = sum2(a0) + sum2(a1);
        g_eproj[((l * ASEL + j + 1) * 4 + which) * 64 + d] = sum2(c0) + sum2(c1);
    }
}

// ---------------- kernel Wprep: bf16 hi/lo Wcat[n][k] (angle weights, 1 block) ----------------
__global__ void __launch_bounds__(128) k_wprep(const float* __restrict__ W_ea1,
                                               const float* __restrict__ W_as)
{
    const int n = threadIdx.x;
    const float* Wsrc = (n < 64) ? W_ea1 : W_as;
    const int nn = n & 63;
    for (int k = 0; k < 64; k++) {
        float w = Wsrc[k * 64 + nn];
        __nv_bfloat16 hi = __float2bfloat16_rn(w);
        __nv_bfloat16 lo = __float2bfloat16_rn(w - __bfloat162float(hi));
        g_Whi[n * 64 + k] = __bfloat16_as_ushort(hi);
        g_Wlo[n * 64 + k] = __bfloat16_as_ushort(lo);
    }
}

// ---------------- kernel Wsymprep: bf16 hi/lo W_sym -> [n=128][k=768] ----------------
__global__ void __launch_bounds__(256) k_wsymprep(const float* __restrict__ W_sym)
{
    const int n = blockIdx.x;            // 0..127
    for (int k = threadIdx.x; k < 768; k += 256) {
        float w = W_sym[k * 128 + n];
        __nv_bfloat16 hi = __float2bfloat16_rn(w);
        __nv_bfloat16 lo = __float2bfloat16_rn(w - __bfloat162float(hi));
        g_WsymH[n * 768 + k] = __bfloat16_as_ushort(hi);
        g_WsymL[n * 768 + k] = __bfloat16_as_ushort(lo);
    }
}

// ---------------- kernel B: edge path + grrg + n_edge (block per node l, 192 thr) ----------------
__global__ void __launch_bounds__(192) k_edge(const float* __restrict__ node_ext,
                                              const float* __restrict__ edge,
                                              const float* __restrict__ h2,
                                              const float* __restrict__ sw,
                                              const int*   __restrict__ nlist,
                                              const float* __restrict__ W_ne,
                                              const float* __restrict__ W_es,
                                              const float* __restrict__ res_e,
                                              float* __restrict__ out_edge)
{
    const int t = threadIdx.x;
    const int l = blockIdx.x;
    __shared__ __align__(16) float e_sm[NNEI][EDIM];
    __shared__ float sw_sm[NNEI];
    __shared__ int   nl_sm[NNEI];
    __shared__ float h2_sm[NNEI][3];
    __shared__ float hg_sm[3 * NDIM + 3 * EDIM];

    {
        const float4* src = (const float4*)(edge + (size_t)l * NNEI * EDIM);
        float4* dst = (float4*)(&e_sm[0][0]);
        for (int i = t; i < NNEI * EDIM / 4; i += 192) dst[i] = src[i];
        for (int i = t; i < NNEI; i += 192) { sw_sm[i] = sw[l * NNEI + i]; nl_sm[i] = nlist[l * NNEI + i]; }
        for (int i = t; i < NNEI * 3; i += 192) h2_sm[i / 3][i % 3] = h2[l * NNEI * 3 + i];
    }
    __syncthreads();

    const bool isA = (t < NDIM);
    const int  d   = t - NDIM;
    ull w2[32];
    if (isA) {
        #pragma unroll
        for (int kk = 0; kk < 32; kk++)
            w2[kk] = pack2(W_ne[(256 + 2 * kk) * NDIM + t], W_ne[(256 + 2 * kk + 1) * NDIM + t]);
    } else {
        #pragma unroll
        for (int kk = 0; kk < 32; kk++)
            w2[kk] = pack2(W_es[(256 + 2 * kk) * EDIM + d], W_es[(256 + 2 * kk + 1) * EDIM + d]);
    }
    const float pv0 = isA ? g_pW0[l * NDIM + t] : g_pV0[l * EDIM + d];
    const float rese0 = isA ? 0.f : res_e[d];
    const unsigned ebase = saddr_of(&e_sm[0][0]);

    float accNE = 0.f, hg0 = 0.f, hg1 = 0.f, hg2 = 0.f;

    // software-pipelined gathers: buffer pb holds group n, pb^1 receives group n+4
    float gproj[2][4], gnode[2][4];
    {
        #pragma unroll
        for (int u = 0; u < 4; u++) {
            int idx = nl_sm[u];
            if (isA) {
                gproj[0][u] = g_pW1[idx * NDIM + t];
                gnode[0][u] = node_ext[idx * NDIM + t];
            } else {
                gproj[0][u] = g_pV1[idx * EDIM + d];
                gnode[0][u] = 0.f;
            }
        }
    }
    int pb = 0;
    for (int n = 0; n < NNEI; n += 4) {
        if (n + 4 < NNEI) {
            #pragma unroll
            for (int u = 0; u < 4; u++) {
                int idx = nl_sm[n + 4 + u];
                if (isA) {
                    gproj[pb ^ 1][u] = g_pW1[idx * NDIM + t];
                    gnode[pb ^ 1][u] = node_ext[idx * NDIM + t];
                } else {
                    gproj[pb ^ 1][u] = g_pV1[idx * EDIM + d];
                }
            }
        }
        #pragma unroll
        for (int up = 0; up < 2; up++) {
            const int n0 = n + 2 * up;
            const unsigned a_n0 = ebase + n0 * 256;
            const unsigned a_n1 = a_n0 + 256;
            ull a0 = 0, a1 = 0, c0 = 0, c1 = 0;
            #pragma unroll
            for (int kk = 0; kk < 16; kk++) {
                ull x0, x1, y0, y1;
                lds_2x64(x0, x1, a_n0 + kk * 16);
                lds_2x64(y0, y1, a_n1 + kk * 16);
                fma2(a0, w2[2 * kk],     x0);
                fma2(a1, w2[2 * kk + 1], x1);
                fma2(c0, w2[2 * kk],     y0);
                fma2(c1, w2[2 * kk + 1], y1);
            }
            float s0 = sum2(a0) + sum2(a1) + pv0 + gproj[pb][2 * up];
            float s1 = sum2(c0) + sum2(c1) + pv0 + gproj[pb][2 * up + 1];
            const float sw0 = sw_sm[n0], sw1 = sw_sm[n0 + 1];
            if (isA) {
                accNE = fmaf(silu_f(s0), sw0, accNE);
                accNE = fmaf(silu_f(s1), sw1, accNE);
                float gw0 = gnode[pb][2 * up] * sw0;
                float gw1 = gnode[pb][2 * up + 1] * sw1;
                hg0 = fmaf(h2_sm[n0][0], gw0, fmaf(h2_sm[n0 + 1][0], gw1, hg0));
                hg1 = fmaf(h2_sm[n0][1], gw0, fmaf(h2_sm[n0 + 1][1], gw1, hg1));
                hg2 = fmaf(h2_sm[n0][2], gw0, fmaf(h2_sm[n0 + 1][2], gw1, hg2));
            } else {
                float ev0 = e_sm[n0][d], ev1 = e_sm[n0 + 1][d];
                out_edge[(l * NNEI + n0)     * EDIM + d] = fmaf(rese0, silu_f(s0), ev0);
                out_edge[(l * NNEI + n0 + 1) * EDIM + d] = fmaf(rese0, silu_f(s1), ev1);
                float ge0 = ev0 * sw0, ge1 = ev1 * sw1;
                hg0 = fmaf(h2_sm[n0][0], ge0, fmaf(h2_sm[n0 + 1][0], ge1, hg0));
                hg1 = fmaf(h2_sm[n0][1], ge0, fmaf(h2_sm[n0 + 1][1], ge1, hg1));
                hg2 = fmaf(h2_sm[n0][2], ge0, fmaf(h2_sm[n0 + 1][2], ge1, hg2));
            }
        }
        pb ^= 1;
    }
    const float inv_nnei = 1.0f / NNEI;
    if (isA) {
        g_nedge[l * NDIM + t] = accNE * inv_nnei;
        hg_sm[0 * NDIM + t] = hg0 * inv_nnei;
        hg_sm[1 * NDIM + t] = hg1 * inv_nnei;
        hg_sm[2 * NDIM + t] = hg2 * inv_nnei;
    } else {
        hg_sm[3 * NDIM + 0 * EDIM + d] = hg0 * inv_nnei;
        hg_sm[3 * NDIM + 1 * EDIM + d] = hg1 * inv_nnei;
        hg_sm[3 * NDIM + 2 * EDIM + d] = hg2 * inv_nnei;
    }
    __syncthreads();

    const float third = 1.0f / 3.0f;
    #pragma unroll
    for (int g = 0; g < 4; g++) {
        int v = t + g * 192;
        float o;
        if (v < 256) {
            int a = v >> 6, dd = v & 63;
            const float* he = hg_sm + 3 * NDIM;
            o = (he[0 * EDIM + a] * he[0 * EDIM + dd] +
                 he[1 * EDIM + a] * he[1 * EDIM + dd] +
                 he[2 * EDIM + a] * he[2 * EDIM + dd]) * third;
        } else {
            int vv = v - 256;
            int a = vv >> 7, c = vv & 127;
            o = (hg_sm[0 * NDIM + a] * hg_sm[0 * NDIM + c] +
                 hg_sm[1 * NDIM + a] * hg_sm[1 * NDIM + c] +
                 hg_sm[2 * NDIM + a] * hg_sm[2 * NDIM + c]) * third;
        }
        g_symin[l * 768 + v] = o;
    }
}

// ---------------- kernel E (tensor): node_sym GEMM via HMMA + finalize ----------------
// Block: 16 nodes x 128 outs, 256 thr (8 warps); warp w owns outs [w*16, w*16+16).
// smem arena layout (bytes): WcH @0 [128][72]us=18432; WcL @18432; Xc @36864 [16][68]f=4352;
// dt aliases @36864 [16][132]f=8448 (used only after all chunks).
#define NF_WCH 0
#define NF_WCL 18432
#define NF_XC  36864
#define NF_DT  36864
__global__ void __launch_bounds__(256) k_node_fin_tc(const float* __restrict__ node,
                                                     const float* __restrict__ b_sym,
                                                     const float* __restrict__ res_n,
                                                     float* __restrict__ out_node)
{
    __shared__ __align__(16) char arena[45568];
    const int t    = threadIdx.x;
    const int lane = t & 31;
    const int w    = t >> 5;
    const int g    = lane >> 2;
    const int tig  = lane & 3;
    const int l0   = blockIdx.x * 16;

    unsigned short* WcH = (unsigned short*)(arena + NF_WCH);  // [128][72]
    unsigned short* WcL = (unsigned short*)(arena + NF_WCL);
    float* Xc = (float*)(arena + NF_XC);                       // [16][68]
    float* dt = (float*)(arena + NF_DT);                       // [16][132]

    const unsigned sWcH = saddr_of(WcH);
    const unsigned sWcL = saddr_of(WcL);
    const unsigned sXc  = saddr_of(Xc);

    float c[2][4] = {{0.f,0.f,0.f,0.f},{0.f,0.f,0.f,0.f}};

    for (int ck = 0; ck < 12; ck++) {
        // stage W slice [128 n][64 k] hi+lo and X chunk [16 rows][64 k]
        {
            const int n = t >> 1, half = t & 1;   // 128 n rows, 2 halves of 32 k
            const unsigned short* srcH = g_WsymH + (size_t)n * 768 + ck * 64 + half * 32;
            const unsigned short* srcL = g_WsymL + (size_t)n * 768 + ck * 64 + half * 32;
            unsigned dH = sWcH + n * 144 + half * 64;
            unsigned dL = sWcL + n * 144 + half * 64;
            #pragma unroll
            for (int i = 0; i < 4; i++) {
                cp_async16(dH + i * 16, srcH + i * 8);
                cp_async16(dL + i * 16, srcL + i * 8);
            }
            const int row = t >> 4, c4 = t & 15;
            cp_async16(sXc + row * 272 + c4 * 16,
                       g_symin + (size_t)(l0 + row) * 768 + ck * 64 + c4 * 4);
            cp_commit();
        }
        cp_wait0();
        __syncthreads();

        #pragma unroll
        for (int q = 0; q < 4; q++) {
            // A frags from Xc (rows g, g+8; k pairs 2tig, 2tig+8)
            unsigned ah[4], al[4];
            {
                float2 v;
                v = *(const float2*)(Xc + g * 68 + 16 * q + 2 * tig);           f2_to_bf(v, ah[0], al[0]);
                v = *(const float2*)(Xc + (g + 8) * 68 + 16 * q + 2 * tig);     f2_to_bf(v, ah[1], al[1]);
                v = *(const float2*)(Xc + g * 68 + 16 * q + 8 + 2 * tig);       f2_to_bf(v, ah[2], al[2]);
                v = *(const float2*)(Xc + (g + 8) * 68 + 16 * q + 8 + 2 * tig); f2_to_bf(v, ah[3], al[3]);
            }
            #pragma unroll
            for (int e = 0; e < 2; e++) {
                const int n = w * 16 + e * 8 + g;
                unsigned bh[2], bl[2];
                bh[0] = *(const unsigned*)((const char*)WcH + n * 144 + (16 * q + 2 * tig) * 2);
                bh[1] = *(const unsigned*)((const char*)WcH + n * 144 + (16 * q + 8 + 2 * tig) * 2);
                bl[0] = *(const unsigned*)((const char*)WcL + n * 144 + (16 * q + 2 * tig) * 2);
                bl[1] = *(const unsigned*)((const char*)WcL + n * 144 + (16 * q + 8 + 2 * tig) * 2);
                mma16816(c[e], ah, bh);
                mma16816(c[e], al, bh);
                mma16816(c[e], ah, bl);
            }
        }
        __syncthreads();   // done reading this chunk's smem before next fill
    }

    // stage D to dt[node][out] (dt aliases Xc region; all chunk reads done)
    #pragma unroll
    for (int e = 0; e < 2; e++) {
        const int nb = w * 16 + e * 8;
        dt[g * 132 + nb + 2 * tig]           = c[e][0];
        dt[g * 132 + nb + 2 * tig + 1]       = c[e][1];
        dt[(g + 8) * 132 + nb + 2 * tig]     = c[e][2];
        dt[(g + 8) * 132 + nb + 2 * tig + 1] = c[e][3];
    }
    __syncthreads();

    // finalize: 2 nodes per pass, coalesced over outs
    {
        const int o = t & 127;
        const float b  = b_sym[o];
        const float r0 = res_n[o], r1 = res_n[128 + o], r2 = res_n[256 + o];
        for (int m = t >> 7; m < 16; m += 2) {
            const int l = l0 + m;
            float ns = silu_f(dt[m * 132 + o] + b);
            out_node[l * NDIM + o] = node[l * NDIM + o]
                                   + r0 * g_pself[l * NDIM + o]
                                   + r1 * ns
                                   + r2 * g_nedge[l * NDIM + o];
        }
    }
}

// ---------------- kernel C: angle path via bf16 HMMA, smem-staged epilogue ----------------
__global__ void __launch_bounds__(128) k_angle_tc(const float* __restrict__ angle,
                                                  const float* __restrict__ a_sw,
                                                  const float* __restrict__ res_a,
                                                  float* __restrict__ out_angle)
{
    const int tid  = threadIdx.x;
    const int l    = blockIdx.x;
    const int lane = tid & 31;
    const int w    = tid >> 5;
    const int g    = lane >> 2;
    const int tig  = lane & 3;
    const int wn   = w * 32;

    __shared__ float bAs[ASEL * 68];
    __shared__ float bBs[ASEL * 68];
    __shared__ float a2s[ASEL * 64];
    __shared__ float b2s[ASEL * 64];
    __shared__ float red[ASEL * 66];
    __shared__ float asw[ASEL];
    __shared__ float resa[64];
    __shared__ __align__(16) float xt[2][8][64];
    __shared__ float dt[8][132];

    const float* ep = g_eproj + (size_t)l * ASEL * 256;
    const float* Xbase = angle + (size_t)l * 400 * 64;

    {
        unsigned sdst = saddr_of(&xt[0][0][0]);
        cp_async16(sdst + tid * 16, Xbase + tid * 4);
        cp_commit();
    }

    for (int idx = tid; idx < ASEL * 64; idx += 128) {
        int j = idx >> 6, d = idx & 63;
        a2s[j * 64 + d] = ep[j * 256 + 0   + d];
        b2s[j * 64 + d] = ep[j * 256 + 128 + d];
        bAs[j * 68 + d] = g_pA1[l * 64 + d] + ep[j * 256 + 64  + d];
        bBs[j * 68 + d] = g_pB1[l * 64 + d] + ep[j * 256 + 192 + d];
    }
    for (int idx = tid; idx < ASEL * 66; idx += 128) red[idx] = 0.f;
    if (tid < ASEL) asw[tid] = a_sw[l * ASEL + tid];
    if (tid < 64)   resa[tid] = res_a[tid];

    unsigned ah[2][4][4], al[2][4][4];
    {
        const unsigned* WhiU = (const unsigned*)g_Whi;
        const unsigned* WloU = (const unsigned*)g_Wlo;
        #pragma unroll
        for (int s = 0; s < 2; s++) {
            int r0 = wn + s * 16 + g;
            int r1 = r0 + 8;
            #pragma unroll
            for (int q = 0; q < 4; q++) {
                int kb = q * 16 + 2 * tig;
                ah[s][q][0] = WhiU[(r0 * 64 + kb) >> 1];
                ah[s][q][1] = WhiU[(r1 * 64 + kb) >> 1];
                ah[s][q][2] = WhiU[(r0 * 64 + kb + 8) >> 1];
                ah[s][q][3] = WhiU[(r1 * 64 + kb + 8) >> 1];
                al[s][q][0] = WloU[(r0 * 64 + kb) >> 1];
                al[s][q][1] = WloU[(r1 * 64 + kb) >> 1];
                al[s][q][2] = WloU[(r0 * 64 + kb + 8) >> 1];
                al[s][q][3] = WloU[(r1 * 64 + kb + 8) >> 1];
            }
        }
    }

    const float inv_sqrt_asel = 0.22360679774997896f;
    int buf = 0;

    for (int tile = 0; tile < 50; tile++) {
        cp_wait0();
        __syncthreads();

        if (tile + 1 < 50) {
            unsigned sdst = saddr_of(&xt[buf ^ 1][0][0]);
            cp_async16(sdst + tid * 16, Xbase + (tile + 1) * 8 * 64 + tid * 4);
            cp_commit();
        }

        {
            const float2* xrow = (const float2*)(&xt[buf][g][0]);
            unsigned bh[4][2], bl[4][2];
            #pragma unroll
            for (int q = 0; q < 4; q++) {
                float2 v0 = xrow[q * 8 + tig];
                float2 v1 = xrow[q * 8 + tig + 4];
                f2_to_bf(v0, bh[q][0], bl[q][0]);
                f2_to_bf(v1, bh[q][1], bl[q][1]);
            }
            float c[2][4] = {{0.f,0.f,0.f,0.f},{0.f,0.f,0.f,0.f}};
            #pragma unroll
            for (int s = 0; s < 2; s++) {
                #pragma unroll
                for (int q = 0; q < 4; q++) {
                    mma16816(c[s], ah[s][q], bh[q]);
                    mma16816(c[s], al[s][q], bh[q]);
                    mma16816(c[s], ah[s][q], bl[q]);
                }
            }
            const int x0 = 2 * tig, x1 = x0 + 1;
            #pragma unroll
            for (int s = 0; s < 2; s++) {
                const int n0 = wn + s * 16 + g;
                dt[x0][n0]     = c[s][0];
                dt[x1][n0]     = c[s][1];
                dt[x0][n0 + 8] = c[s][2];
                dt[x1][n0 + 8] = c[s][3];
            }
        }
        __syncthreads();

        if (tid < 64) {
            const int d = tid;
            #pragma unroll
            for (int r = 0; r < 8; r++) {
                int x = tile * 8 + r;
                int i = x / 20, j = x - i * 20;
                float vA = silu_f(dt[r][d] + bAs[i * 68 + d] + a2s[j * 64 + d]);
                red[i * 66 + d] += asw[j] * vA;
            }
        } else {
            const int m = tid - 64;
            #pragma unroll
            for (int r = 0; r < 8; r++) {
                int x = tile * 8 + r;
                int i = x / 20, j = x - i * 20;
                float vB = silu_f(dt[r][64 + m] + bBs[i * 68 + m] + b2s[j * 64 + m]);
                out_angle[(size_t)(l * 400 + x) * 64 + m] =
                    fmaf(resa[m], vB, xt[buf][r][m]);
            }
        }
        buf ^= 1;
    }
    __syncthreads();
    for (int idx = tid; idx < ASEL * 64; idx += 128) {
        int i = idx >> 6, d = idx & 63;
        g_red[((size_t)l * ASEL + i) * 64 + d] = red[i * 66 + d] * asw[i] * inv_sqrt_asel;
    }
}

// ---------------- kernel D: e_angle_msg GEMM + edge finalize (2 nodes / block) ----------------
__global__ void __launch_bounds__(128) k_eamsg(const float* __restrict__ W_ea2,
                                               const float* __restrict__ b_ea2,
                                               const float* __restrict__ res_e,
                                               float* __restrict__ out_edge)
{
    const int t = threadIdx.x;
    const int d = t & 63;
    const int l = blockIdx.x * 2 + (t >> 6);
    ull w2[32];
    #pragma unroll
    for (int kk = 0; kk < 32; kk++)
        w2[kk] = pack2(W_ea2[(2 * kk) * 64 + d], W_ea2[(2 * kk + 1) * 64 + d]);
    const float b   = b_ea2[d];
    const float re1 = res_e[64 + d];

    __shared__ __align__(16) float xs[2][ASEL][64];
    {
        const float4* src = (const float4*)(g_red + (size_t)(blockIdx.x * 2) * ASEL * 64);
        float4* dst = (float4*)(&xs[0][0][0]);
        for (int q = t; q < 2 * ASEL * 16; q += 128) dst[q] = src[q];
    }
    __syncthreads();

    const unsigned xbase = saddr_of(&xs[t >> 6][0][0]);
    const float ypad = re1 * silu_f(b);
    for (int i = 0; i < NNEI; i++) {
        float add;
        if (i < ASEL) {
            const unsigned a_i = xbase + i * 256;
            ull a0 = 0, a1 = 0;
            #pragma unroll
            for (int kk = 0; kk < 16; kk++) {
                ull x0, x1;
                lds_2x64(x0, x1, a_i + kk * 16);
                fma2(a0, w2[2 * kk],     x0);
                fma2(a1, w2[2 * kk + 1], x1);
            }
            add = re1 * silu_f(sum2(a0) + sum2(a1) + b);
        } else {
            add = ypad;
        }
        const size_t o = (size_t)(l * NNEI + i) * 64 + d;
        out_edge[o] += add;
    }
}

// ---------------- stream/event resources (created once, at load time) ----------------
struct HxStreams {
    cudaStream_t s1 = nullptr;
    cudaEvent_t  evNP = nullptr, evEdge = nullptr, evJoin = nullptr;
    bool ok = false;
    HxStreams() {
        ok = (cudaStreamCreateWithFlags(&s1, cudaStreamNonBlocking) == cudaSuccess) &&
             (cudaEventCreateWithFlags(&evNP,   cudaEventDisableTiming) == cudaSuccess) &&
             (cudaEventCreateWithFlags(&evEdge, cudaEventDisableTiming) == cudaSuccess) &&
             (cudaEventCreateWithFlags(&evJoin, cudaEventDisableTiming) == cudaSuccess);
    }
};
static HxStreams g_hx;

// ---------------- launch ----------------
extern "C" void kernel_launch(void* const* d_in, const int* in_sizes, int n_in,
                              void* d_out, int out_size)
{
    (void)in_sizes; (void)n_in; (void)out_size;
    const float* node_ext = (const float*)d_in[0];
    const float* edge     = (const float*)d_in[1];
    const float* h2       = (const float*)d_in[2];
    const float* angle    = (const float*)d_in[3];
    const float* sw       = (const float*)d_in[4];
    const float* a_sw     = (const float*)d_in[5];
    const float* W_self   = (const float*)d_in[6];
    const float* b_self   = (const float*)d_in[7];
    const float* W_sym    = (const float*)d_in[8];
    const float* b_sym    = (const float*)d_in[9];
    const float* W_ne     = (const float*)d_in[10];
    const float* b_ne     = (const float*)d_in[11];
    const float* W_es     = (const float*)d_in[12];
    const float* b_es     = (const float*)d_in[13];
    const float* W_ea1    = (const float*)d_in[14];
    const float* b_ea1    = (const float*)d_in[15];
    const float* W_ea2    = (const float*)d_in[16];
    const float* b_ea2    = (const float*)d_in[17];
    const float* W_as     = (const float*)d_in[18];
    const float* b_as     = (const float*)d_in[19];
    const float* res_n    = (const float*)d_in[20];
    const float* res_e    = (const float*)d_in[21];
    const float* res_a    = (const float*)d_in[22];
    const int*   nlist    = (const int*)d_in[23];

    float* out_node  = (float*)d_out;
    float* out_edge  = out_node + NLOC * NDIM;
    float* out_angle = out_edge + NLOC * NNEI * EDIM;

    if (g_hx.ok) {
        cudaStream_t s0 = 0, s1 = g_hx.s1;
        k_wsymprep<<<128, 256, 0, s0>>>(W_sym);
        k_nodeproj<<<dim3(NLOC / 16, 5), 128, 0, s0>>>(node_ext, W_self, b_self, W_ne, b_ne,
                                                       W_es, b_es, W_ea1, b_ea1, W_as, b_as);
        cudaEventRecord(g_hx.evNP, s0);
        k_wprep<<<1, 128, 0, s1>>>(W_ea1, W_as);
        k_eproj<<<NLOC, 256, 0, s1>>>(edge, W_ea1, W_as);
        cudaStreamWaitEvent(s1, g_hx.evNP, 0);
        k_edge<<<NLOC, 192, 0, s0>>>(node_ext, edge, h2, sw, nlist, W_ne, W_es, res_e, out_edge);
        cudaEventRecord(g_hx.evEdge, s0);
        k_angle_tc<<<NLOC, 128, 0, s1>>>(angle, a_sw, res_a, out_angle);
        k_node_fin_tc<<<NLOC / 16, 256, 0, s0>>>(node_ext, b_sym, res_n, out_node);
        cudaStreamWaitEvent(s1, g_hx.evEdge, 0);
        k_eamsg<<<NLOC / 2, 128, 0, s1>>>(W_ea2, b_ea2, res_e, out_edge);
        cudaEventRecord(g_hx.evJoin, s1);
        cudaStreamWaitEvent(s0, g_hx.evJoin, 0);
    } else {
        k_wsymprep<<<128, 256>>>(W_sym);
        k_nodeproj<<<dim3(NLOC / 16, 5), 128>>>(node_ext, W_self, b_self, W_ne, b_ne,
                                                W_es, b_es, W_ea1, b_ea1, W_as, b_as);
        k_wprep<<<1, 128>>>(W_ea1, W_as);
        k_eproj<<<NLOC, 256>>>(edge, W_ea1, W_as);
        k_edge<<<NLOC, 192>>>(node_ext, edge, h2, sw, nlist, W_ne, W_es, res_e, out_edge);
        k_node_fin_tc<<<NLOC / 16, 256>>>(node_ext, b_sym, res_n, out_node);
        k_angle_tc<<<NLOC, 128>>>(angle, a_sw, res_a, out_angle);
        k_eamsg<<<NLOC / 2, 128>>>(W_ea2, b_ea2, res_e, out_edge);
    }
}

// round 17
// speedup vs baseline: 1.0676x; 1.0676x over previous
#include <cuda_runtime.h>
#include <cuda_bf16.h>

#define NLOC 1024
#define NNEI 64
#define NDIM 128
#define EDIM 64
#define ADIM 64
#define ASEL 20

typedef unsigned long long ull;

// ---------------- scratch (static device memory; no allocation) ----------------
__device__ float g_pself[NLOC * NDIM];
__device__ float g_pW0[NLOC * NDIM];
__device__ float g_pW1[NLOC * NDIM];
__device__ float g_pV0[NLOC * EDIM];
__device__ float g_pV1[NLOC * EDIM];
__device__ float g_pA1[NLOC * EDIM];
__device__ float g_pB1[NLOC * ADIM];
__device__ float g_eproj[NLOC * ASEL * 4 * 64]; // [l][j][A2,A3,B2,B3][64]
__device__ float g_red[NLOC * ASEL * EDIM];
__device__ float g_symin[NLOC * 768];
__device__ float g_nedge[NLOC * NDIM];
// bf16 hi/lo W for the angle MMA A operand: Wcat[n=128][k=64], plain k-major
__device__ unsigned short g_Whi[128 * 64];
__device__ unsigned short g_Wlo[128 * 64];

// ---------------- helpers ----------------
__device__ __forceinline__ float silu_f(float x) { return __fdividef(x, 1.0f + __expf(-x)); }

__device__ __forceinline__ ull pack2(float lo, float hi) {
    ull r;
    asm("mov.b64 %0, {%1, %2};" : "=l"(r) : "f"(lo), "f"(hi));
    return r;
}
__device__ __forceinline__ float sum2(ull v) {
    float lo, hi;
    asm("mov.b64 {%0, %1}, %2;" : "=f"(lo), "=f"(hi) : "l"(v));
    return lo + hi;
}
__device__ __forceinline__ void fma2(ull &acc, ull a, ull b) {
    asm("fma.rn.f32x2 %0, %1, %2, %0;" : "+l"(acc) : "l"(a), "l"(b));
}
__device__ __forceinline__ void lds_2x64(ull &a, ull &b, unsigned saddr) {
    asm volatile("ld.shared.v2.u64 {%0, %1}, [%2];" : "=l"(a), "=l"(b) : "r"(saddr));
}
__device__ __forceinline__ unsigned saddr_of(const void* p) {
    return (unsigned)__cvta_generic_to_shared(p);
}
__device__ __forceinline__ void cp_async16(unsigned sdst, const void* gsrc) {
    asm volatile("cp.async.cg.shared.global [%0], [%1], 16;" :: "r"(sdst), "l"(gsrc));
}
__device__ __forceinline__ void cp_commit() { asm volatile("cp.async.commit_group;"); }
__device__ __forceinline__ void cp_wait0()  { asm volatile("cp.async.wait_group 0;"); }

// bf16 HMMA (base ISA, sm_80+): D[16x8 f32] += A[16x16 bf16] * B[16x8 bf16]
__device__ __forceinline__ void mma16816(float* c, const unsigned* a, const unsigned* b) {
    asm volatile("mma.sync.aligned.m16n8k16.row.col.f32.bf16.bf16.f32 "
        "{%0,%1,%2,%3}, {%4,%5,%6,%7}, {%8,%9}, {%0,%1,%2,%3};"
        : "+f"(c[0]), "+f"(c[1]), "+f"(c[2]), "+f"(c[3])
        : "r"(a[0]), "r"(a[1]), "r"(a[2]), "r"(a[3]), "r"(b[0]), "r"(b[1]));
}
// fast hi/lo: packed cvt + shift-residual (x -> low half, y -> high half)
__device__ __forceinline__ void f2_to_bf(float2 v, unsigned &hi, unsigned &lo) {
    unsigned h;
    asm("cvt.rn.bf16x2.f32 %0, %1, %2;" : "=r"(h) : "f"(v.y), "f"(v.x));
    float hx = __uint_as_float(h << 16);
    float hy = __uint_as_float(h & 0xFFFF0000u);
    float rx = v.x - hx;
    float ry = v.y - hy;
    asm("cvt.rn.bf16x2.f32 %0, %1, %2;" : "=r"(lo) : "f"(ry), "f"(rx));
    hi = h;
}

// ---------------- kernel A: per-node projections (16 nodes / block, pass = blockIdx.y) ----------------
__global__ void __launch_bounds__(128) k_nodeproj(
        const float* __restrict__ node,
        const float* __restrict__ W_self, const float* __restrict__ b_self,
        const float* __restrict__ W_ne,   const float* __restrict__ b_ne,
        const float* __restrict__ W_es,   const float* __restrict__ b_es,
        const float* __restrict__ W_ea1,  const float* __restrict__ b_ea1,
        const float* __restrict__ W_as,   const float* __restrict__ b_as)
{
    const int t    = threadIdx.x;
    const int l0   = blockIdx.x * 16;
    const int pass = blockIdx.y;
    __shared__ __align__(16) float xs[16][NDIM];
    {
        const float4* src = (const float4*)(node + l0 * NDIM);
        float4* dst = (float4*)(&xs[0][0]);
        #pragma unroll
        for (int i = 0; i < 4; i++) dst[t + 128 * i] = src[t + 128 * i];
    }
    __syncthreads();

    float acc[16];
    #pragma unroll
    for (int m = 0; m < 16; m++) acc[m] = 0.f;

    if (pass < 3) {
        const float* W = (pass == 0) ? W_self : ((pass == 1) ? W_ne : (W_ne + NDIM * NDIM));
        for (int k = 0; k < NDIM; k += 4) {
            float w0 = W[(k + 0) * NDIM + t];
            float w1 = W[(k + 1) * NDIM + t];
            float w2 = W[(k + 2) * NDIM + t];
            float w3 = W[(k + 3) * NDIM + t];
            #pragma unroll
            for (int m = 0; m < 16; m++) {
                float4 x = *(const float4*)(&xs[m][k]);
                acc[m] = fmaf(x.x, w0, acc[m]);
                acc[m] = fmaf(x.y, w1, acc[m]);
                acc[m] = fmaf(x.z, w2, acc[m]);
                acc[m] = fmaf(x.w, w3, acc[m]);
            }
        }
        if (pass == 0) {
            float b = b_self[t];
            #pragma unroll
            for (int m = 0; m < 16; m++) g_pself[(l0 + m) * NDIM + t] = silu_f(acc[m] + b);
        } else if (pass == 1) {
            float b = b_ne[t];
            #pragma unroll
            for (int m = 0; m < 16; m++) g_pW0[(l0 + m) * NDIM + t] = acc[m] + b;
        } else {
            #pragma unroll
            for (int m = 0; m < 16; m++) g_pW1[(l0 + m) * NDIM + t] = acc[m];
        }
    } else {
        const int d = t & 63;
        const float* W;
        if (pass == 3) W = W_es + ((t < 64) ? 0 : NDIM * EDIM) + d;
        else           W = ((t < 64) ? W_ea1 : W_as) + 64 * 64 + d;
        for (int k = 0; k < NDIM; k += 4) {
            float w0 = W[(k + 0) * 64];
            float w1 = W[(k + 1) * 64];
            float w2 = W[(k + 2) * 64];
            float w3 = W[(k + 3) * 64];
            #pragma unroll
            for (int m = 0; m < 16; m++) {
                float4 x = *(const float4*)(&xs[m][k]);
                acc[m] = fmaf(x.x, w0, acc[m]);
                acc[m] = fmaf(x.y, w1, acc[m]);
                acc[m] = fmaf(x.z, w2, acc[m]);
                acc[m] = fmaf(x.w, w3, acc[m]);
            }
        }
        if (pass == 3) {
            if (t < 64) {
                float b = b_es[d];
                #pragma unroll
                for (int m = 0; m < 16; m++) g_pV0[(l0 + m) * EDIM + d] = acc[m] + b;
            } else {
                #pragma unroll
                for (int m = 0; m < 16; m++) g_pV1[(l0 + m) * EDIM + d] = acc[m];
            }
        } else {
            if (t < 64) {
                float b = b_ea1[d];
                #pragma unroll
                for (int m = 0; m < 16; m++) g_pA1[(l0 + m) * EDIM + d] = acc[m] + b;
            } else {
                float b = b_as[d];
                #pragma unroll
                for (int m = 0; m < 16; m++) g_pB1[(l0 + m) * ADIM + d] = acc[m] + b;
            }
        }
    }
}

// ---------------- kernel A2: e_ang projections; 1 node / block ----------------
__global__ void __launch_bounds__(256) k_eproj(const float* __restrict__ edge,
                                               const float* __restrict__ W_ea1,
                                               const float* __restrict__ W_as)
{
    const int t  = threadIdx.x;
    const int l  = blockIdx.x;
    const int which = t >> 6;        // 0:A2 1:A3 2:B2 3:B3
    const int d = t & 63;
    const float* Wsrc = ((which < 2) ? W_ea1 : W_as) + ((which & 1) ? 256 * 64 : 192 * 64) + d;
    ull w2[32];
    #pragma unroll
    for (int kk = 0; kk < 32; kk++)
        w2[kk] = pack2(Wsrc[(2 * kk) * 64], Wsrc[(2 * kk + 1) * 64]);

    __shared__ __align__(16) float rows[ASEL][64];
    const unsigned rbase = saddr_of(&rows[0][0]);

    {
        const float4* src = (const float4*)(edge + (size_t)l * NNEI * EDIM);
        float4* dst = (float4*)(&rows[0][0]);
        for (int q = t; q < ASEL * 16; q += 256) dst[q] = src[q];
    }
    __syncthreads();
    for (int j = 0; j < ASEL; j += 2) {
        const unsigned a_j0 = rbase + j * 256;
        const unsigned a_j1 = a_j0 + 256;
        ull a0 = 0, a1 = 0, c0 = 0, c1 = 0;
        #pragma unroll
        for (int kk = 0; kk < 16; kk++) {
            ull x0, x1, y0, y1;
            lds_2x64(x0, x1, a_j0 + kk * 16);
            lds_2x64(y0, y1, a_j1 + kk * 16);
            fma2(a0, w2[2 * kk],     x0);
            fma2(a1, w2[2 * kk + 1], x1);
            fma2(c0, w2[2 * kk],     y0);
            fma2(c1, w2[2 * kk + 1], y1);
        }
        g_eproj[((l * ASEL + j)     * 4 + which) * 64 + d] = sum2(a0) + sum2(a1);
        g_eproj[((l * ASEL + j + 1) * 4 + which) * 64 + d] = sum2(c0) + sum2(c1);
    }
}

// ---------------- kernel Wprep: bf16 hi/lo Wcat[n][k] (angle weights, 1 block) ----------------
__global__ void __launch_bounds__(128) k_wprep(const float* __restrict__ W_ea1,
                                               const float* __restrict__ W_as)
{
    const int n = threadIdx.x;
    const float* Wsrc = (n < 64) ? W_ea1 : W_as;
    const int nn = n & 63;
    for (int k = 0; k < 64; k++) {
        float w = Wsrc[k * 64 + nn];
        __nv_bfloat16 hi = __float2bfloat16_rn(w);
        __nv_bfloat16 lo = __float2bfloat16_rn(w - __bfloat162float(hi));
        g_Whi[n * 64 + k] = __bfloat16_as_ushort(hi);
        g_Wlo[n * 64 + k] = __bfloat16_as_ushort(lo);
    }
}

// ---------------- kernel B: edge path + grrg + n_edge (block per node l, 192 thr) ----------------
__global__ void __launch_bounds__(192) k_edge(const float* __restrict__ node_ext,
                                              const float* __restrict__ edge,
                                              const float* __restrict__ h2,
                                              const float* __restrict__ sw,
                                              const int*   __restrict__ nlist,
                                              const float* __restrict__ W_ne,
                                              const float* __restrict__ W_es,
                                              const float* __restrict__ res_e,
                                              float* __restrict__ out_edge)
{
    const int t = threadIdx.x;
    const int l = blockIdx.x;
    __shared__ __align__(16) float e_sm[NNEI][EDIM];
    __shared__ float sw_sm[NNEI];
    __shared__ int   nl_sm[NNEI];
    __shared__ float h2_sm[NNEI][3];
    __shared__ float hg_sm[3 * NDIM + 3 * EDIM];

    {
        const float4* src = (const float4*)(edge + (size_t)l * NNEI * EDIM);
        float4* dst = (float4*)(&e_sm[0][0]);
        for (int i = t; i < NNEI * EDIM / 4; i += 192) dst[i] = src[i];
        for (int i = t; i < NNEI; i += 192) { sw_sm[i] = sw[l * NNEI + i]; nl_sm[i] = nlist[l * NNEI + i]; }
        for (int i = t; i < NNEI * 3; i += 192) h2_sm[i / 3][i % 3] = h2[l * NNEI * 3 + i];
    }
    __syncthreads();

    const bool isA = (t < NDIM);
    const int  d   = t - NDIM;
    ull w2[32];
    if (isA) {
        #pragma unroll
        for (int kk = 0; kk < 32; kk++)
            w2[kk] = pack2(W_ne[(256 + 2 * kk) * NDIM + t], W_ne[(256 + 2 * kk + 1) * NDIM + t]);
    } else {
        #pragma unroll
        for (int kk = 0; kk < 32; kk++)
            w2[kk] = pack2(W_es[(256 + 2 * kk) * EDIM + d], W_es[(256 + 2 * kk + 1) * EDIM + d]);
    }
    const float pv0 = isA ? g_pW0[l * NDIM + t] : g_pV0[l * EDIM + d];
    const float rese0 = isA ? 0.f : res_e[d];
    const unsigned ebase = saddr_of(&e_sm[0][0]);

    float accNE = 0.f, hg0 = 0.f, hg1 = 0.f, hg2 = 0.f;

    // software-pipelined gathers: buffer pb holds group n, pb^1 receives group n+4
    float gproj[2][4], gnode[2][4];
    #pragma unroll
    for (int u = 0; u < 4; u++) {
        int idx = nl_sm[u];
        if (isA) {
            gproj[0][u] = g_pW1[idx * NDIM + t];
            gnode[0][u] = node_ext[idx * NDIM + t];
        } else {
            gproj[0][u] = g_pV1[idx * EDIM + d];
            gnode[0][u] = 0.f;
        }
    }
    int pb = 0;
    for (int n = 0; n < NNEI; n += 4) {
        if (n + 4 < NNEI) {
            #pragma unroll
            for (int u = 0; u < 4; u++) {
                int idx = nl_sm[n + 4 + u];
                if (isA) {
                    gproj[pb ^ 1][u] = g_pW1[idx * NDIM + t];
                    gnode[pb ^ 1][u] = node_ext[idx * NDIM + t];
                } else {
                    gproj[pb ^ 1][u] = g_pV1[idx * EDIM + d];
                }
            }
        }
        #pragma unroll
        for (int up = 0; up < 2; up++) {
            const int n0 = n + 2 * up;
            const unsigned a_n0 = ebase + n0 * 256;
            const unsigned a_n1 = a_n0 + 256;
            ull a0 = 0, a1 = 0, c0 = 0, c1 = 0;
            #pragma unroll
            for (int kk = 0; kk < 16; kk++) {
                ull x0, x1, y0, y1;
                lds_2x64(x0, x1, a_n0 + kk * 16);
                lds_2x64(y0, y1, a_n1 + kk * 16);
                fma2(a0, w2[2 * kk],     x0);
                fma2(a1, w2[2 * kk + 1], x1);
                fma2(c0, w2[2 * kk],     y0);
                fma2(c1, w2[2 * kk + 1], y1);
            }
            float s0 = sum2(a0) + sum2(a1) + pv0 + gproj[pb][2 * up];
            float s1 = sum2(c0) + sum2(c1) + pv0 + gproj[pb][2 * up + 1];
            const float sw0 = sw_sm[n0], sw1 = sw_sm[n0 + 1];
            if (isA) {
                accNE = fmaf(silu_f(s0), sw0, accNE);
                accNE = fmaf(silu_f(s1), sw1, accNE);
                float gw0 = gnode[pb][2 * up] * sw0;
                float gw1 = gnode[pb][2 * up + 1] * sw1;
                hg0 = fmaf(h2_sm[n0][0], gw0, fmaf(h2_sm[n0 + 1][0], gw1, hg0));
                hg1 = fmaf(h2_sm[n0][1], gw0, fmaf(h2_sm[n0 + 1][1], gw1, hg1));
                hg2 = fmaf(h2_sm[n0][2], gw0, fmaf(h2_sm[n0 + 1][2], gw1, hg2));
            } else {
                float ev0 = e_sm[n0][d], ev1 = e_sm[n0 + 1][d];
                out_edge[(l * NNEI + n0)     * EDIM + d] = fmaf(rese0, silu_f(s0), ev0);
                out_edge[(l * NNEI + n0 + 1) * EDIM + d] = fmaf(rese0, silu_f(s1), ev1);
                float ge0 = ev0 * sw0, ge1 = ev1 * sw1;
                hg0 = fmaf(h2_sm[n0][0], ge0, fmaf(h2_sm[n0 + 1][0], ge1, hg0));
                hg1 = fmaf(h2_sm[n0][1], ge0, fmaf(h2_sm[n0 + 1][1], ge1, hg1));
                hg2 = fmaf(h2_sm[n0][2], ge0, fmaf(h2_sm[n0 + 1][2], ge1, hg2));
            }
        }
        pb ^= 1;
    }
    const float inv_nnei = 1.0f / NNEI;
    if (isA) {
        g_nedge[l * NDIM + t] = accNE * inv_nnei;
        hg_sm[0 * NDIM + t] = hg0 * inv_nnei;
        hg_sm[1 * NDIM + t] = hg1 * inv_nnei;
        hg_sm[2 * NDIM + t] = hg2 * inv_nnei;
    } else {
        hg_sm[3 * NDIM + 0 * EDIM + d] = hg0 * inv_nnei;
        hg_sm[3 * NDIM + 1 * EDIM + d] = hg1 * inv_nnei;
        hg_sm[3 * NDIM + 2 * EDIM + d] = hg2 * inv_nnei;
    }
    __syncthreads();

    const float third = 1.0f / 3.0f;
    #pragma unroll
    for (int g = 0; g < 4; g++) {
        int v = t + g * 192;
        float o;
        if (v < 256) {
            int a = v >> 6, dd = v & 63;
            const float* he = hg_sm + 3 * NDIM;
            o = (he[0 * EDIM + a] * he[0 * EDIM + dd] +
                 he[1 * EDIM + a] * he[1 * EDIM + dd] +
                 he[2 * EDIM + a] * he[2 * EDIM + dd]) * third;
        } else {
            int vv = v - 256;
            int a = vv >> 7, c = vv & 127;
            o = (hg_sm[0 * NDIM + a] * hg_sm[0 * NDIM + c] +
                 hg_sm[1 * NDIM + a] * hg_sm[1 * NDIM + c] +
                 hg_sm[2 * NDIM + a] * hg_sm[2 * NDIM + c]) * third;
        }
        g_symin[l * 768 + v] = o;
    }
}

// ---------------- kernel E: node_sym GEMM + finalize (4 nodes / block, split-k 4, 512 thr) ----------------
__global__ void __launch_bounds__(512) k_node_fin(const float* __restrict__ node,
                                                  const float* __restrict__ W_sym,
                                                  const float* __restrict__ b_sym,
                                                  const float* __restrict__ res_n,
                                                  float* __restrict__ out_node)
{
    const int t  = threadIdx.x;
    const int tt = t & 127;
    const int q  = t >> 7;
    const int l0 = blockIdx.x * 4;
    __shared__ __align__(16) float xs[4][768];
    __shared__ float part[3][4][NDIM];
    {
        const float4* src = (const float4*)(g_symin + (size_t)l0 * 768);
        float4* dst = (float4*)(&xs[0][0]);
        for (int i = t; i < 768; i += 512) dst[i] = src[i];
    }
    __syncthreads();

    float acc[4] = {0.f, 0.f, 0.f, 0.f};
    const int k0 = q * 192;
    #pragma unroll 2
    for (int k = k0; k < k0 + 192; k += 4) {
        float w0 = W_sym[(k + 0) * NDIM + tt];
        float w1 = W_sym[(k + 1) * NDIM + tt];
        float w2 = W_sym[(k + 2) * NDIM + tt];
        float w3 = W_sym[(k + 3) * NDIM + tt];
        #pragma unroll
        for (int m = 0; m < 4; m++) {
            float4 x = *(const float4*)(&xs[m][k]);
            acc[m] = fmaf(x.x, w0, acc[m]);
            acc[m] = fmaf(x.y, w1, acc[m]);
            acc[m] = fmaf(x.z, w2, acc[m]);
            acc[m] = fmaf(x.w, w3, acc[m]);
        }
    }
    if (q > 0) {
        #pragma unroll
        for (int m = 0; m < 4; m++) part[q - 1][m][tt] = acc[m];
    }
    __syncthreads();
    if (q == 0) {
        const float b  = b_sym[tt];
        const float r0 = res_n[tt], r1 = res_n[NDIM + tt], r2 = res_n[2 * NDIM + tt];
        #pragma unroll
        for (int m = 0; m < 4; m++) {
            const int l = l0 + m;
            float s = acc[m] + part[0][m][tt] + part[1][m][tt] + part[2][m][tt] + b;
            float ns = silu_f(s);
            out_node[l * NDIM + tt] = node[l * NDIM + tt]
                                    + r0 * g_pself[l * NDIM + tt]
                                    + r1 * ns
                                    + r2 * g_nedge[l * NDIM + tt];
        }
    }
}

// ---------------- kernel C: angle path via bf16 HMMA, smem-staged epilogue ----------------
__global__ void __launch_bounds__(128) k_angle_tc(const float* __restrict__ angle,
                                                  const float* __restrict__ a_sw,
                                                  const float* __restrict__ res_a,
                                                  float* __restrict__ out_angle)
{
    const int tid  = threadIdx.x;
    const int l    = blockIdx.x;
    const int lane = tid & 31;
    const int w    = tid >> 5;
    const int g    = lane >> 2;
    const int tig  = lane & 3;
    const int wn   = w * 32;

    __shared__ float bAs[ASEL * 68];
    __shared__ float bBs[ASEL * 68];
    __shared__ float a2s[ASEL * 64];
    __shared__ float b2s[ASEL * 64];
    __shared__ float red[ASEL * 66];
    __shared__ float asw[ASEL];
    __shared__ float resa[64];
    __shared__ __align__(16) float xt[2][8][64];
    __shared__ float dt[8][132];

    const float* ep = g_eproj + (size_t)l * ASEL * 256;
    const float* Xbase = angle + (size_t)l * 400 * 64;

    {
        unsigned sdst = saddr_of(&xt[0][0][0]);
        cp_async16(sdst + tid * 16, Xbase + tid * 4);
        cp_commit();
    }

    for (int idx = tid; idx < ASEL * 64; idx += 128) {
        int j = idx >> 6, d = idx & 63;
        a2s[j * 64 + d] = ep[j * 256 + 0   + d];
        b2s[j * 64 + d] = ep[j * 256 + 128 + d];
        bAs[j * 68 + d] = g_pA1[l * 64 + d] + ep[j * 256 + 64  + d];
        bBs[j * 68 + d] = g_pB1[l * 64 + d] + ep[j * 256 + 192 + d];
    }
    for (int idx = tid; idx < ASEL * 66; idx += 128) red[idx] = 0.f;
    if (tid < ASEL) asw[tid] = a_sw[l * ASEL + tid];
    if (tid < 64)   resa[tid] = res_a[tid];

    unsigned ah[2][4][4], al[2][4][4];
    {
        const unsigned* WhiU = (const unsigned*)g_Whi;
        const unsigned* WloU = (const unsigned*)g_Wlo;
        #pragma unroll
        for (int s = 0; s < 2; s++) {
            int r0 = wn + s * 16 + g;
            int r1 = r0 + 8;
            #pragma unroll
            for (int q = 0; q < 4; q++) {
                int kb = q * 16 + 2 * tig;
                ah[s][q][0] = WhiU[(r0 * 64 + kb) >> 1];
                ah[s][q][1] = WhiU[(r1 * 64 + kb) >> 1];
                ah[s][q][2] = WhiU[(r0 * 64 + kb + 8) >> 1];
                ah[s][q][3] = WhiU[(r1 * 64 + kb + 8) >> 1];
                al[s][q][0] = WloU[(r0 * 64 + kb) >> 1];
                al[s][q][1] = WloU[(r1 * 64 + kb) >> 1];
                al[s][q][2] = WloU[(r0 * 64 + kb + 8) >> 1];
                al[s][q][3] = WloU[(r1 * 64 + kb + 8) >> 1];
            }
        }
    }

    const float inv_sqrt_asel = 0.22360679774997896f;
    int buf = 0;

    for (int tile = 0; tile < 50; tile++) {
        cp_wait0();
        __syncthreads();

        if (tile + 1 < 50) {
            unsigned sdst = saddr_of(&xt[buf ^ 1][0][0]);
            cp_async16(sdst + tid * 16, Xbase + (tile + 1) * 8 * 64 + tid * 4);
            cp_commit();
        }

        {
            const float2* xrow = (const float2*)(&xt[buf][g][0]);
            unsigned bh[4][2], bl[4][2];
            #pragma unroll
            for (int q = 0; q < 4; q++) {
                float2 v0 = xrow[q * 8 + tig];
                float2 v1 = xrow[q * 8 + tig + 4];
                f2_to_bf(v0, bh[q][0], bl[q][0]);
                f2_to_bf(v1, bh[q][1], bl[q][1]);
            }
            float c[2][4] = {{0.f,0.f,0.f,0.f},{0.f,0.f,0.f,0.f}};
            #pragma unroll
            for (int s = 0; s < 2; s++) {
                #pragma unroll
                for (int q = 0; q < 4; q++) {
                    mma16816(c[s], ah[s][q], bh[q]);
                    mma16816(c[s], al[s][q], bh[q]);
                    mma16816(c[s], ah[s][q], bl[q]);
                }
            }
            const int x0 = 2 * tig, x1 = x0 + 1;
            #pragma unroll
            for (int s = 0; s < 2; s++) {
                const int n0 = wn + s * 16 + g;
                dt[x0][n0]     = c[s][0];
                dt[x1][n0]     = c[s][1];
                dt[x0][n0 + 8] = c[s][2];
                dt[x1][n0 + 8] = c[s][3];
            }
        }
        __syncthreads();

        if (tid < 64) {
            const int d = tid;
            #pragma unroll
            for (int r = 0; r < 8; r++) {
                int x = tile * 8 + r;
                int i = x / 20, j = x - i * 20;
                float vA = silu_f(dt[r][d] + bAs[i * 68 + d] + a2s[j * 64 + d]);
                red[i * 66 + d] += asw[j] * vA;
            }
        } else {
            const int m = tid - 64;
            #pragma unroll
            for (int r = 0; r < 8; r++) {
                int x = tile * 8 + r;
                int i = x / 20, j = x - i * 20;
                float vB = silu_f(dt[r][64 + m] + bBs[i * 68 + m] + b2s[j * 64 + m]);
                out_angle[(size_t)(l * 400 + x) * 64 + m] =
                    fmaf(resa[m], vB, xt[buf][r][m]);
            }
        }
        buf ^= 1;
    }
    __syncthreads();
    for (int idx = tid; idx < ASEL * 64; idx += 128) {
        int i = idx >> 6, d = idx & 63;
        g_red[((size_t)l * ASEL + i) * 64 + d] = red[i * 66 + d] * asw[i] * inv_sqrt_asel;
    }
}

// ---------------- kernel D: e_angle_msg GEMM + edge finalize (2 nodes / block) ----------------
__global__ void __launch_bounds__(128) k_eamsg(const float* __restrict__ W_ea2,
                                               const float* __restrict__ b_ea2,
                                               const float* __restrict__ res_e,
                                               float* __restrict__ out_edge)
{
    const int t = threadIdx.x;
    const int d = t & 63;
    const int l = blockIdx.x * 2 + (t >> 6);
    ull w2[32];
    #pragma unroll
    for (int kk = 0; kk < 32; kk++)
        w2[kk] = pack2(W_ea2[(2 * kk) * 64 + d], W_ea2[(2 * kk + 1) * 64 + d]);
    const float b   = b_ea2[d];
    const float re1 = res_e[64 + d];

    __shared__ __align__(16) float xs[2][ASEL][64];
    {
        const float4* src = (const float4*)(g_red + (size_t)(blockIdx.x * 2) * ASEL * 64);
        float4* dst = (float4*)(&xs[0][0][0]);
        for (int q = t; q < 2 * ASEL * 16; q += 128) dst[q] = src[q];
    }
    __syncthreads();

    const unsigned xbase = saddr_of(&xs[t >> 6][0][0]);
    const float ypad = re1 * silu_f(b);
    for (int i = 0; i < NNEI; i++) {
        float add;
        if (i < ASEL) {
            const unsigned a_i = xbase + i * 256;
            ull a0 = 0, a1 = 0;
            #pragma unroll
            for (int kk = 0; kk < 16; kk++) {
                ull x0, x1;
                lds_2x64(x0, x1, a_i + kk * 16);
                fma2(a0, w2[2 * kk],     x0);
                fma2(a1, w2[2 * kk + 1], x1);
            }
            add = re1 * silu_f(sum2(a0) + sum2(a1) + b);
        } else {
            add = ypad;
        }
        const size_t o = (size_t)(l * NNEI + i) * 64 + d;
        out_edge[o] += add;
    }
}

// ---------------- stream/event resources (created once, at load time) ----------------
struct HxStreams {
    cudaStream_t s1 = nullptr;
    cudaEvent_t  evNP = nullptr, evEdge = nullptr, evJoin = nullptr;
    bool ok = false;
    HxStreams() {
        ok = (cudaStreamCreateWithFlags(&s1, cudaStreamNonBlocking) == cudaSuccess) &&
             (cudaEventCreateWithFlags(&evNP,   cudaEventDisableTiming) == cudaSuccess) &&
             (cudaEventCreateWithFlags(&evEdge, cudaEventDisableTiming) == cudaSuccess) &&
             (cudaEventCreateWithFlags(&evJoin, cudaEventDisableTiming) == cudaSuccess);
    }
};
static HxStreams g_hx;

// ---------------- launch ----------------
extern "C" void kernel_launch(void* const* d_in, const int* in_sizes, int n_in,
                              void* d_out, int out_size)
{
    (void)in_sizes; (void)n_in; (void)out_size;
    const float* node_ext = (const float*)d_in[0];
    const float* edge     = (const float*)d_in[1];
    const float* h2       = (const float*)d_in[2];
    const float* angle    = (const float*)d_in[3];
    const float* sw       = (const float*)d_in[4];
    const float* a_sw     = (const float*)d_in[5];
    const float* W_self   = (const float*)d_in[6];
    const float* b_self   = (const float*)d_in[7];
    const float* W_sym    = (const float*)d_in[8];
    const float* b_sym    = (const float*)d_in[9];
    const float* W_ne     = (const float*)d_in[10];
    const float* b_ne     = (const float*)d_in[11];
    const float* W_es     = (const float*)d_in[12];
    const float* b_es     = (const float*)d_in[13];
    const float* W_ea1    = (const float*)d_in[14];
    const float* b_ea1    = (const float*)d_in[15];
    const float* W_ea2    = (const float*)d_in[16];
    const float* b_ea2    = (const float*)d_in[17];
    const float* W_as     = (const float*)d_in[18];
    const float* b_as     = (const float*)d_in[19];
    const float* res_n    = (const float*)d_in[20];
    const float* res_e    = (const float*)d_in[21];
    const float* res_a    = (const float*)d_in[22];
    const int*   nlist    = (const int*)d_in[23];

    float* out_node  = (float*)d_out;
    float* out_edge  = out_node + NLOC * NDIM;
    float* out_angle = out_edge + NLOC * NNEI * EDIM;

    if (g_hx.ok) {
        cudaStream_t s0 = 0, s1 = g_hx.s1;
        k_nodeproj<<<dim3(NLOC / 16, 5), 128, 0, s0>>>(node_ext, W_self, b_self, W_ne, b_ne,
                                                       W_es, b_es, W_ea1, b_ea1, W_as, b_as);
        cudaEventRecord(g_hx.evNP, s0);
        k_wprep<<<1, 128, 0, s1>>>(W_ea1, W_as);
        k_eproj<<<NLOC, 256, 0, s1>>>(edge, W_ea1, W_as);
        cudaStreamWaitEvent(s1, g_hx.evNP, 0);
        k_edge<<<NLOC, 192, 0, s0>>>(node_ext, edge, h2, sw, nlist, W_ne, W_es, res_e, out_edge);
        cudaEventRecord(g_hx.evEdge, s0);
        k_angle_tc<<<NLOC, 128, 0, s1>>>(angle, a_sw, res_a, out_angle);
        k_node_fin<<<NLOC / 4, 512, 0, s0>>>(node_ext, W_sym, b_sym, res_n, out_node);
        cudaStreamWaitEvent(s1, g_hx.evEdge, 0);
        k_eamsg<<<NLOC / 2, 128, 0, s1>>>(W_ea2, b_ea2, res_e, out_edge);
        cudaEventRecord(g_hx.evJoin, s1);
        cudaStreamWaitEvent(s0, g_hx.evJoin, 0);
    } else {
        k_nodeproj<<<dim3(NLOC / 16, 5), 128>>>(node_ext, W_self, b_self, W_ne, b_ne,
                                                W_es, b_es, W_ea1, b_ea1, W_as, b_as);
        k_wprep<<<1, 128>>>(W_ea1, W_as);
        k_eproj<<<NLOC, 256>>>(edge, W_ea1, W_as);
        k_edge<<<NLOC, 192>>>(node_ext, edge, h2, sw, nlist, W_ne, W_es, res_e, out_edge);
        k_node_fin<<<NLOC / 4, 512>>>(node_ext, W_sym, b_sym, res_n, out_node);
        k_angle_tc<<<NLOC, 128>>>(angle, a_sw, res_a, out_angle);
        k_eamsg<<<NLOC / 2, 128>>>(W_ea2, b_ea2, res_e, out_edge);
    }
}